// round 16
// baseline (speedup 1.0000x reference)
#include <cuda_runtime.h>
#include <math.h>

#define NB    4      // batch
#define S     363    // sinogram length / recon grid
#define A     180    // angles
#define ASP   3      // backproject angle splits
#define AH    60     // angles per split
#define W     256    // output size
#define RP    364    // table row entries, k in [0,363]

#define HW(d) (-2.0f / ((float)(M_PI * M_PI) * (float)(d) * (float)(d)))

// tab2[pair][a][k] = (mid_b0, delta_b0, mid_b1, delta_b1) for batches
// (2*pair, 2*pair+1): delta = p[k]-p[k-1], mid = p[k-1]+0.5*delta, p[-1]=p[363]=0.
// Interp at q (=pos+1, round k of q-0.5): mid + t*delta, t = (q-0.5)-k.
__device__ float4 g_tab2[2][A * RP];
// angle-split partials, same layout as out: [split][n][yy][xx]
__device__ float g_part[ASP][NB * W * W];

// One block per (n, a) column, 192 threads. Thread u computes the output PAIR
// (2u, 2u+1): odd-distance taps mean one aligned LDS.64 feeds tap d of output
// 2u and tap d+-2 of output 2u+1, halving LDS count. All weights immediates.
__global__ __launch_bounds__(192) void ramp_filter_kernel(const float* __restrict__ x) {
    const int na = blockIdx.x;
    const int n  = na / A;
    const int a  = na - n * A;

    __shared__ __align__(16) float xsp[1092]; // zeros[0,364) | x[364,727) | zeros
    __shared__ float ps[S + 2];               // p[-1..363], zero ends

    const int t = threadIdx.x;
    for (int i = t; i < 1092; i += 192) xsp[i] = 0.0f;
    if (t < 2) ps[t * 364] = 0.0f;            // ps[0]=p[-1]=0, ps[364]=p[363]=0
    __syncthreads();
    // input layout: [n][1][s][a], a fastest
    for (int s = t; s < S; s += 192)
        xsp[364 + s] = x[(n * S + s) * A + a];
    __syncthreads();

    if (t < 182) {
        const float* c = xsp + 364 + 2 * t;   // &x[te], te = 2t (even output)
        // acc0 = p[te], acc1 = p[te+1]
        // edges: acc0: center, right d=1, left d=361; acc1: center, left e=1,
        // right e=361 (reads padded zeros when out of data range).
        float acc0 = 0.5f * c[0] + HW(1) * c[1] + HW(361) * c[-361];
        float acc1 = 0.5f * c[1] + HW(1) * c[0] + HW(361) * c[362];
        #pragma unroll
        for (int m = 0; m < 180; ++m) {
            const int d = 2 * m + 1;          // 1..359
            const float2 L = *(const float2*)(c - d - 1); // (x[te-d-1], x[te-d])
            acc0 = fmaf(L.y, HW(d),     acc0);            // left tap d of te
            acc1 = fmaf(L.x, HW(d + 2), acc1);            // left tap d+2 of te+1
            const float2 R = *(const float2*)(c + d + 1); // (x[te+1+d], x[te+d+2])
            acc1 = fmaf(R.x, HW(d),     acc1);            // right tap d of te+1
            acc0 = fmaf(R.y, HW(d + 2), acc0);            // right tap d+2 of te
        }
        ps[2 * t + 1] = acc0;
        if (2 * t + 1 < S) ps[2 * t + 2] = acc1;
    }
    __syncthreads();

    // write this batch's (mid, delta) half of the packed pair table
    float2* gr = ((float2*)&g_tab2[n >> 1][(size_t)a * RP]) + (n & 1);
    for (int k = t; k < RP; k += 192) {       // k in [0, 363]
        const float p0 = ps[k];               // p[k-1]
        const float p1 = ps[k + 1];           // p[k]
        const float d  = p1 - p0;
        gr[2 * k] = make_float2(fmaf(0.5f, d, p0), d);
    }
}

#define CH 2                     // angles per pipeline chunk
#define NCHUNK (AH / CH)         // 30, even
#define MAGICF 12582912.0f       // 2^23 + 2^22
#define MAGICI 0x4B400000

// grid (8, 32, 3): block = 32(x) x 8(y) spatial tile x angle-third; warp =
// 8(x) x 4(y) patch for gather locality. ALL 4 batches per thread: one index
// feeds two LDG.128. qp = xf*cos - yf*sin + 181.5; k = round(qp) via magic;
// value = mid + (qp-k)*delta.
__global__ __launch_bounds__(256) void backproject_kernel() {
    const int x0 = blockIdx.x * 32;
    const int y0 = blockIdx.y * 8;
    const int hf = blockIdx.z;
    const int abase = hf * AH;
    const int tid = threadIdx.x;
    const int w = tid >> 5, l = tid & 31;

    const int xx = x0 + ((w & 3) << 3) + (l & 7);
    const int yy = y0 + ((w >> 2) << 2) + (l >> 3);

    __shared__ float2 sc2[AH];   // (cos, sin) for angle abase+t

    if (tid < AH) {
        float sn, cs;
        sincosf((float)(abase + tid) * (float)(M_PI / 180.0), &sn, &cs);
        sc2[tid] = make_float2(cs, sn);
    }
    __syncthreads();

    const float xf = (float)(xx - 128);
    const float yf = (float)(yy - 128);
    const float4* __restrict__ tb0 = g_tab2[0] + (size_t)abase * RP;
    const float4* __restrict__ tb1 = g_tab2[1] + (size_t)abase * RP;

    float accm0 = 0.f, accm1 = 0.f, accm2 = 0.f, accm3 = 0.f;
    float accd0 = 0.f, accd1 = 0.f, accd2 = 0.f, accd3 = 0.f;

    float4 va0[CH], va1[CH], vb0[CH], vb1[CH];
    float  wa[CH], wb[CH];

    #define LOADC(c, v0, v1, ww)                                              \
        {                                                                     \
            const int a0 = (c) * CH;                                          \
            _Pragma("unroll")                                                 \
            for (int k = 0; k < CH; ++k) {                                    \
                const float2 cb = sc2[a0 + k];                                \
                const float qp = fmaf(xf, cb.x, fmaf(-yf, cb.y, 181.5f));     \
                const float f  = qp + MAGICF;                                 \
                const float il = f - MAGICF;             /* round(qp) */      \
                ww[k] = qp - il;                         /* in [-.5,.5] */    \
                const int i = (a0 + k) * RP + (__float_as_int(f) - MAGICI);   \
                v0[k] = __ldg(tb0 + i);                                       \
                v1[k] = __ldg(tb1 + i);                                       \
            }                                                                 \
        }

    #define ACCC(v0, v1, ww)                                                  \
        {                                                                     \
            _Pragma("unroll")                                                 \
            for (int k = 0; k < CH; ++k) {                                    \
                accm0 += v0[k].x;  accd0 = fmaf(ww[k], v0[k].y, accd0);       \
                accm1 += v0[k].z;  accd1 = fmaf(ww[k], v0[k].w, accd1);       \
                accm2 += v1[k].x;  accd2 = fmaf(ww[k], v1[k].y, accd2);       \
                accm3 += v1[k].z;  accd3 = fmaf(ww[k], v1[k].w, accd3);       \
            }                                                                 \
        }

    LOADC(0, va0, va1, wa)
    LOADC(1, vb0, vb1, wb)
    #pragma unroll 1
    for (int c = 0; c + 2 < NCHUNK; c += 2) {
        ACCC(va0, va1, wa)
        LOADC(c + 2, va0, va1, wa)
        ACCC(vb0, vb1, wb)
        LOADC(c + 3, vb0, vb1, wb)
    }
    ACCC(va0, va1, wa)
    ACCC(vb0, vb1, wb)

    #undef LOADC
    #undef ACCC

    float* o = g_part[hf] + (size_t)yy * W + xx;
    o[0 * W * W] = accm0 + accd0;
    o[1 * W * W] = accm1 + accd1;
    o[2 * W * W] = accm2 + accd2;
    o[3 * W * W] = accm3 + accd3;
}

// out = (part0 + part1 + part2) * pi/360, fully coalesced float4.
__global__ __launch_bounds__(256) void combine_kernel(float* __restrict__ out) {
    const int i = blockIdx.x * 256 + threadIdx.x;     // float4 index
    const float4 p0 = ((const float4*)g_part[0])[i];
    const float4 p1 = ((const float4*)g_part[1])[i];
    const float4 p2 = ((const float4*)g_part[2])[i];
    const float sc = (float)(M_PI / 360.0);
    float4 r;
    r.x = (p0.x + p1.x + p2.x) * sc;
    r.y = (p0.y + p1.y + p2.y) * sc;
    r.z = (p0.z + p1.z + p2.z) * sc;
    r.w = (p0.w + p1.w + p2.w) * sc;
    ((float4*)out)[i] = r;
}

extern "C" void kernel_launch(void* const* d_in, const int* in_sizes, int n_in,
                              void* d_out, int out_size) {
    const float* x = (const float*)d_in[0];
    float* out = (float*)d_out;

    ramp_filter_kernel<<<NB * A, 192>>>(x);
    backproject_kernel<<<dim3(8, 32, ASP), 256>>>();
    combine_kernel<<<(NB * W * W / 4) / 256, 256>>>(out);
}

// round 17
// speedup vs baseline: 1.2964x; 1.2964x over previous
#include <cuda_runtime.h>
#include <math.h>

#define NB    4      // batch
#define S     363    // sinogram length / recon grid
#define A     180    // angles
#define AH    90     // angles per half
#define W     256    // output size
#define RP    364    // table row entries, k in [0,363]

#define HW(d) (-2.0f / ((float)(M_PI * M_PI) * (float)(d) * (float)(d)))

// tab2[pair][a][k] = (mid_b0, delta_b0, mid_b1, delta_b1) for batches
// (2*pair, 2*pair+1): delta = p[k]-p[k-1], mid = p[k-1]+0.5*delta, p[-1]=p[363]=0.
// Interp at q (=pos+1, round k of q-0.5): mid + t*delta, t = (q-0.5)-k.
__device__ float4 g_tab2[2][A * RP];
// angle-half partials, same layout as out: [half][n][yy][xx]
__device__ float g_part[2][NB * W * W];

// One block per (n, a) column. Thread t0 computes outputs {t0, t0+182}
// (even spacing -> shared tap parity). One odd-offset sweep off in [-181,361]:
// consecutive lanes read consecutive addresses (1 wavefront per LDS.32) and
// every weight is a compile-time immediate. Offsets where ALL lanes would read
// zero padding are deleted (their taps are exactly the zero-padded region).
__global__ __launch_bounds__(384) void ramp_filter_kernel(const float* __restrict__ x) {
    const int na = blockIdx.x;
    const int n  = na / A;
    const int a  = na - n * A;

    __shared__ float xsp[728];    // zeros[0,181) | x[181,544) | zeros[544,728)
    __shared__ float ps[S + 2];   // p[-1..363], zero ends

    const int t = threadIdx.x;
    for (int i = t; i < 728; i += 384) xsp[i] = 0.0f;
    if (t < 2) ps[t * 364] = 0.0f;       // ps[0]=p[-1]=0, ps[364]=p[363]=0
    __syncthreads();
    // input layout: [n][1][s][a], a fastest
    for (int s = t; s < S; s += 384)
        xsp[181 + s] = x[(n * S + s) * A + a];
    __syncthreads();

    if (t < 182) {
        const float* c = xsp + 181 + t;  // &x[t0]
        float acc0 = 0.5f * c[0];        // center of output t0
        float acc1 = 0.5f * c[182];      // center of output t0+182
        #pragma unroll
        for (int j = 0; j < 272; ++j) {
            const int off = -181 + 2 * j;            // odd, in [-181, 361]
            const float v = c[off];
            acc0 = fmaf(v, HW(off), acc0);           // tap d=off of output t0
            if (off >= -179)                          // d = off-182 in [-361,179]
                acc1 = fmaf(v, HW(off - 182), acc1); // tap of output t0+182
        }
        ps[t + 1] = acc0;
        if (t < 181) ps[t + 183] = acc1;
    }
    __syncthreads();

    // write this batch's (mid, delta) half of the packed pair table
    float2* gr = ((float2*)&g_tab2[n >> 1][(size_t)a * RP]) + (n & 1);
    for (int k = t; k < RP; k += 384) {  // k in [0, 363]
        const float p0 = ps[k];          // p[k-1]
        const float p1 = ps[k + 1];      // p[k]
        const float d  = p1 - p0;
        gr[2 * k] = make_float2(fmaf(0.5f, d, p0), d);
    }
}

#define CH 2                     // angles per pipeline chunk
#define NCHUNK (AH / CH)         // 45 (odd -> explicit pipeline tail below)
#define MAGICF 12582912.0f       // 2^23 + 2^22
#define MAGICI 0x4B400000

// grid (8, 32, 2): block = 32(x) x 8(y) spatial tile x angle-half; warp =
// 8(x) x 4(y) patch for gather locality. ALL 4 batches per thread: one index
// feeds two LDG.128. qp = xf*cos - yf*sin + 181.5; k = round(qp) via magic;
// value = mid + (qp-k)*delta.
__global__ __launch_bounds__(256) void backproject_kernel() {
    const int x0 = blockIdx.x * 32;
    const int y0 = blockIdx.y * 8;
    const int hf = blockIdx.z;
    const int abase = hf * AH;
    const int tid = threadIdx.x;
    const int w = tid >> 5, l = tid & 31;

    const int xx = x0 + ((w & 3) << 3) + (l & 7);
    const int yy = y0 + ((w >> 2) << 2) + (l >> 3);

    __shared__ float2 sc2[AH];   // (cos, sin) for angle abase+t

    if (tid < AH) {
        float sn, cs;
        sincosf((float)(abase + tid) * (float)(M_PI / 180.0), &sn, &cs);
        sc2[tid] = make_float2(cs, sn);
    }
    __syncthreads();

    const float xf = (float)(xx - 128);
    const float yf = (float)(yy - 128);
    const float4* __restrict__ tb0 = g_tab2[0] + (size_t)abase * RP;
    const float4* __restrict__ tb1 = g_tab2[1] + (size_t)abase * RP;

    float accm0 = 0.f, accm1 = 0.f, accm2 = 0.f, accm3 = 0.f;
    float accd0 = 0.f, accd1 = 0.f, accd2 = 0.f, accd3 = 0.f;

    float4 va0[CH], va1[CH], vb0[CH], vb1[CH];
    float  wa[CH], wb[CH];

    #define LOADC(c, v0, v1, ww)                                              \
        {                                                                     \
            const int a0 = (c) * CH;                                          \
            _Pragma("unroll")                                                 \
            for (int k = 0; k < CH; ++k) {                                    \
                const float2 cb = sc2[a0 + k];                                \
                const float qp = fmaf(xf, cb.x, fmaf(-yf, cb.y, 181.5f));     \
                const float f  = qp + MAGICF;                                 \
                const float il = f - MAGICF;             /* round(qp) */      \
                ww[k] = qp - il;                         /* in [-.5,.5] */    \
                const int i = (a0 + k) * RP + (__float_as_int(f) - MAGICI);   \
                v0[k] = __ldg(tb0 + i);                                       \
                v1[k] = __ldg(tb1 + i);                                       \
            }                                                                 \
        }

    #define ACCC(v0, v1, ww)                                                  \
        {                                                                     \
            _Pragma("unroll")                                                 \
            for (int k = 0; k < CH; ++k) {                                    \
                accm0 += v0[k].x;  accd0 = fmaf(ww[k], v0[k].y, accd0);       \
                accm1 += v0[k].z;  accd1 = fmaf(ww[k], v0[k].w, accd1);       \
                accm2 += v1[k].x;  accd2 = fmaf(ww[k], v1[k].y, accd2);       \
                accm3 += v1[k].z;  accd3 = fmaf(ww[k], v1[k].w, accd3);       \
            }                                                                 \
        }

    // Double-buffered pipeline over NCHUNK=45 chunks (odd), explicit tail.
    LOADC(0, va0, va1, wa)
    LOADC(1, vb0, vb1, wb)
    int c = 0;
    #pragma unroll 1
    for (; c + 3 < NCHUNK; c += 2) {
        ACCC(va0, va1, wa)
        LOADC(c + 2, va0, va1, wa)
        ACCC(vb0, vb1, wb)
        LOADC(c + 3, vb0, vb1, wb)
    }
    // here: va holds chunk c (=NCHUNK-3), vb holds c+1; chunk c+2 = NCHUNK-1 remains
    ACCC(va0, va1, wa)
    LOADC(c + 2, va0, va1, wa)
    ACCC(vb0, vb1, wb)
    ACCC(va0, va1, wa)

    #undef LOADC
    #undef ACCC

    float* o = g_part[hf] + (size_t)yy * W + xx;
    o[0 * W * W] = accm0 + accd0;
    o[1 * W * W] = accm1 + accd1;
    o[2 * W * W] = accm2 + accd2;
    o[3 * W * W] = accm3 + accd3;
}

// out = (part0 + part1) * pi/360, fully coalesced float4.
__global__ __launch_bounds__(256) void combine_kernel(float* __restrict__ out) {
    const int i = blockIdx.x * 256 + threadIdx.x;     // float4 index
    const float4 p0 = ((const float4*)g_part[0])[i];
    const float4 p1 = ((const float4*)g_part[1])[i];
    const float sc = (float)(M_PI / 360.0);
    float4 r;
    r.x = (p0.x + p1.x) * sc;
    r.y = (p0.y + p1.y) * sc;
    r.z = (p0.z + p1.z) * sc;
    r.w = (p0.w + p1.w) * sc;
    ((float4*)out)[i] = r;
}

extern "C" void kernel_launch(void* const* d_in, const int* in_sizes, int n_in,
                              void* d_out, int out_size) {
    const float* x = (const float*)d_in[0];
    float* out = (float*)d_out;

    ramp_filter_kernel<<<NB * A, 384>>>(x);
    backproject_kernel<<<dim3(8, 32, 2), 256>>>();
    combine_kernel<<<(NB * W * W / 4) / 256, 256>>>(out);
}